// round 8
// baseline (speedup 1.0000x reference)
#include <cuda_runtime.h>
#include <cuda_bf16.h>
#include <math.h>
#include <stdint.h>

#define NN 50000
#define NE 500000
#define HID 64
#define HEADS 8
#define NCLS 10
#define MPAD 50048            // 782 * 64
#define F0ROWS 30080          // 235*128
#define F1ROWS 20096          // 157*128
#define F0SZ (F0ROWS * 256)
#define FSZ  (F0SZ + F1ROWS * 128)
#define NBLK 196              // scan blocks: 196*256 = 50176 >= NN

// ---------------- scratch -----------------------------------------------
__device__ float g_bufA[(size_t)NN * 512];
__device__ float g_bufB[(size_t)NN * 512];
__device__ float g_elA[NN * HEADS];
__device__ float g_erA[NN * HEADS];
__device__ float g_elB[NN * HEADS];
__device__ float g_erB[NN * HEADS];
__device__ int   g_deg[NN];
__device__ int   g_rowptr[NN + 1];
__device__ int   g_cursor[NN];
__device__ int   g_csrsrc[NE];
__device__ int   g_blksum[256];
__device__ int   g_blkoff[256];
__device__ __nv_bfloat16 g_f_hi[FSZ];
__device__ __nv_bfloat16 g_f_lo[FSZ];
__device__ __nv_bfloat16 g_h_hi[(size_t)MPAD * 64];
__device__ __nv_bfloat16 g_h_lo[(size_t)MPAD * 64];
__device__ __nv_bfloat16 g_a_hi[(size_t)MPAD * 512];
__device__ __nv_bfloat16 g_a_lo[(size_t)MPAD * 512];
__device__ __nv_bfloat16 g_wf0_hi[64 * 256], g_wf0_lo[64 * 256];
__device__ __nv_bfloat16 g_wf1_hi[64 * 128], g_wf1_lo[64 * 128];
__device__ __nv_bfloat16 g_w0t_hi[512 * 64], g_w0t_lo[512 * 64];
__device__ __nv_bfloat16 g_w1t_hi[512 * 512], g_w1t_lo[512 * 512];

// ---------------- PTX helpers --------------------------------------------
__device__ __forceinline__ uint32_t smem_u32(const void* p) {
    uint32_t a;
    asm("{ .reg .u64 t; cvta.to.shared.u64 t, %1; cvt.u32.u64 %0, t; }" : "=r"(a) : "l"(p));
    return a;
}
__device__ __forceinline__ void cp_async16(uint32_t s, const void* g) {
    asm volatile("cp.async.cg.shared.global [%0], [%1], 16;" :: "r"(s), "l"(g));
}
#define CP_COMMIT() asm volatile("cp.async.commit_group;" ::: "memory")

__device__ __forceinline__ void ldsm_x4(uint32_t& r0, uint32_t& r1, uint32_t& r2, uint32_t& r3,
                                        uint32_t addr) {
    asm volatile("ldmatrix.sync.aligned.m8n8.x4.shared.b16 {%0,%1,%2,%3}, [%4];"
                 : "=r"(r0), "=r"(r1), "=r"(r2), "=r"(r3) : "r"(addr));
}
__device__ __forceinline__ void mma_bf16(float* d, const uint32_t* a, const uint32_t* b) {
    asm volatile(
        "mma.sync.aligned.m16n8k16.row.col.f32.bf16.bf16.f32 "
        "{%0,%1,%2,%3}, {%4,%5,%6,%7}, {%8,%9}, {%0,%1,%2,%3};"
        : "+f"(d[0]), "+f"(d[1]), "+f"(d[2]), "+f"(d[3])
        : "r"(a[0]), "r"(a[1]), "r"(a[2]), "r"(a[3]), "r"(b[0]), "r"(b[1]));
}

// ---------------- graph preprocessing ---------------------------------------
__global__ void k_zero_deg() {
    int i = blockIdx.x * blockDim.x + threadIdx.x;
    if (i < NN) g_deg[i] = 0;
}
__global__ void k_zero_el() {
    int i = blockIdx.x * blockDim.x + threadIdx.x;
    if (i < NN * HEADS) {
        g_elA[i] = 0.f; g_erA[i] = 0.f;
        g_elB[i] = 0.f; g_erB[i] = 0.f;
    }
}
__global__ void k_count(const int* __restrict__ dst, int E) {
    int e = blockIdx.x * blockDim.x + threadIdx.x;
    if (e < E) atomicAdd(&g_deg[dst[e]], 1);
}
__global__ void k_scan1() {
    __shared__ int sh[256];
    int b = blockIdx.x, t = threadIdx.x;
    int i = b * 256 + t;
    int v = (i < NN) ? g_deg[i] : 0;
    sh[t] = v;
    __syncthreads();
#pragma unroll
    for (int off = 1; off < 256; off <<= 1) {
        int x = (t >= off) ? sh[t - off] : 0;
        __syncthreads();
        sh[t] += x;
        __syncthreads();
    }
    if (i < NN) g_rowptr[i] = sh[t] - v;
    if (t == 255) g_blksum[b] = sh[255];
}
__global__ void k_scan2() {
    __shared__ int sh[256];
    int t = threadIdx.x;
    int v = (t < NBLK) ? g_blksum[t] : 0;
    sh[t] = v;
    __syncthreads();
#pragma unroll
    for (int off = 1; off < 256; off <<= 1) {
        int x = (t >= off) ? sh[t - off] : 0;
        __syncthreads();
        sh[t] += x;
        __syncthreads();
    }
    if (t < NBLK) g_blkoff[t] = sh[t] - v;
    if (t == 255) g_rowptr[NN] = sh[255];
}
__global__ void k_scan3() {
    int i = blockIdx.x * blockDim.x + threadIdx.x;
    if (i < NN) {
        int r = g_rowptr[i] + g_blkoff[i >> 8];
        g_rowptr[i] = r;
        g_cursor[i] = r;
    }
}
__global__ void k_scatter(const int* __restrict__ src, const int* __restrict__ dst, int E) {
    int e = blockIdx.x * blockDim.x + threadIdx.x;
    if (e < E) {
        int pos = atomicAdd(&g_cursor[dst[e]], 1);
        g_csrsrc[pos] = src[e];
    }
}

// ---------------- weight transpose + bf16 split -----------------------------
__global__ void k_tsplit(const float* __restrict__ W, __nv_bfloat16* __restrict__ Thi,
                         __nv_bfloat16* __restrict__ Tlo, int K, int N)
{
    __shared__ float s[32][33];
    int tx = threadIdx.x, ty = threadIdx.y;
    int k = blockIdx.y * 32 + ty, n = blockIdx.x * 32 + tx;
    s[ty][tx] = W[(size_t)k * N + n];
    __syncthreads();
    int n2 = blockIdx.x * 32 + ty, k2 = blockIdx.y * 32 + tx;
    float v = s[tx][ty];
    __nv_bfloat16 h = __float2bfloat16(v);
    Thi[(size_t)n2 * K + k2] = h;
    Tlo[(size_t)n2 * K + k2] = __float2bfloat16(v - __bfloat162float(h));
}

__global__ void k_asplit(const float* __restrict__ A, __nv_bfloat16* __restrict__ hi,
                         __nv_bfloat16* __restrict__ lo, int count)
{
    int i = (blockIdx.x * blockDim.x + threadIdx.x) * 4;
    if (i >= count) return;
    float4 v = *reinterpret_cast<const float4*>(A + i);
    __nv_bfloat162 h0, h1, l0, l1;
    h0.x = __float2bfloat16(v.x); h0.y = __float2bfloat16(v.y);
    h1.x = __float2bfloat16(v.z); h1.y = __float2bfloat16(v.w);
    l0.x = __float2bfloat16(v.x - __bfloat162float(h0.x));
    l0.y = __float2bfloat16(v.y - __bfloat162float(h0.y));
    l1.x = __float2bfloat16(v.z - __bfloat162float(h1.x));
    l1.y = __float2bfloat16(v.w - __bfloat162float(h1.y));
    *reinterpret_cast<__nv_bfloat162*>(hi + i) = h0;
    *reinterpret_cast<__nv_bfloat162*>(hi + i + 2) = h1;
    *reinterpret_cast<__nv_bfloat162*>(lo + i) = l0;
    *reinterpret_cast<__nv_bfloat162*>(lo + i + 2) = l1;
}

// ---------------- generalized bf16 3x-split mma GEMM -------------------------
// Unified MI=2 tiles: proj = BM128 x BN64, layers = BM64 x BN128.
// 4-stage cp.async pipeline, one __syncthreads per chunk, 3 CTAs/SM.
#define ROWB 48
#define STG 4
template <int KDIM, int BM, int BN, bool FUSE, bool SPLIT_OUT>
__global__ __launch_bounds__(256, 3) void k_mma(
    const __nv_bfloat16* __restrict__ Ahi, const __nv_bfloat16* __restrict__ Alo,
    const __nv_bfloat16* __restrict__ Bhi, const __nv_bfloat16* __restrict__ Blo,
    float* __restrict__ C,
    __nv_bfloat16* __restrict__ Ohi, __nv_bfloat16* __restrict__ Olo,
    const float* __restrict__ bias,
    const float* __restrict__ al, const float* __restrict__ ar,
    float* __restrict__ el, float* __restrict__ er,
    int M)
{
    constexpr int NCH = KDIM / 16;
    constexpr int MI = 2;
    constexpr int ATILE = BM * ROWB;
    constexpr int BTILE = BN * ROWB;
    constexpr int BUFB = 2 * ATILE + 2 * BTILE;   // 18432 for both layouts
    extern __shared__ char smem[];
    uint32_t sb = smem_u32(smem);

    const int tid = threadIdx.x;
    const int wid = tid >> 5, lane = tid & 31;
    const int bm = blockIdx.y * BM;
    const int bn = blockIdx.x * BN;
    const int wm = (BN == 128) ? (wid & 1) * 32 : (wid & 3) * 32;
    const int wn = (BN == 128) ? (wid >> 1) * 32 : (wid >> 2) * 32;

    // ---- load mappings ----
    const int lhalf = tid & 1;
    // A: BM=128 -> every thread loads one 16B into BOTH hi and lo tiles (row tid>>1)
    //    BM=64  -> threads <128 load hi, threads >=128 load lo (row (tid&127)>>1)
    const int arow = (BM == 128) ? (tid >> 1) : ((tid & 127) >> 1);
    const __nv_bfloat16* gAh = Ahi + (size_t)(bm + arow) * KDIM + lhalf * 8;
    const __nv_bfloat16* gAl = Alo + (size_t)(bm + arow) * KDIM + lhalf * 8;
    const uint32_t sA = arow * ROWB + lhalf * 16;
    // B: BN=128 -> every thread loads (row tid>>1) into hi and lo tiles
    //    BN=64  -> threads <128 only
    const bool bOK = (BN == 128) || (tid < 128);
    const int brow = (BN == 128) ? (tid >> 1) : ((tid & 127) >> 1);
    const __nv_bfloat16* gBh = Bhi + (size_t)(bn + brow) * KDIM + lhalf * 8;
    const __nv_bfloat16* gBl = Blo + (size_t)(bn + brow) * KDIM + lhalf * 8;
    const uint32_t sB = brow * ROWB + lhalf * 16;

    auto load_chunk = [&](int c) {
        uint32_t base = sb + (c % STG) * BUFB;
        int k0 = c * 16;
        if (BM == 128) {
            cp_async16(base + sA,         gAh + k0);
            cp_async16(base + ATILE + sA, gAl + k0);
        } else {
            if (tid < 128) cp_async16(base + sA,         gAh + k0);
            else           cp_async16(base + ATILE + sA, gAl + k0);
        }
        if (bOK) {
            cp_async16(base + 2 * ATILE + sB,         gBh + k0);
            cp_async16(base + 2 * ATILE + BTILE + sB, gBl + k0);
        }
    };

    float acc[MI][4][4];
#pragma unroll
    for (int i = 0; i < MI; i++)
#pragma unroll
        for (int j = 0; j < 4; j++)
#pragma unroll
            for (int k = 0; k < 4; k++) acc[i][j][k] = 0.f;

    // prologue: fill STG-1 stages
#pragma unroll
    for (int c = 0; c < STG - 1 && c < NCH; c++) {
        load_chunk(c);
        CP_COMMIT();
    }

    const uint32_t a_off = (wm + (lane & 15)) * ROWB + (lane >> 4) * 16;
    const uint32_t b_off = (wn + (lane & 7) + ((lane >> 4) << 3)) * ROWB + (((lane >> 3) & 1) * 16);

    for (int c = 0; c < NCH; c++) {
        const uint32_t base = sb + (c % STG) * BUFB;
        asm volatile("cp.async.wait_group %0;" :: "n"(STG - 2));
        __syncthreads();

        if (c + STG - 1 < NCH) load_chunk(c + STG - 1);
        CP_COMMIT();

        uint32_t ahi[MI][4], alo[MI][4], bhi[4][2], blo[4][2];
#pragma unroll
        for (int mi = 0; mi < MI; mi++) {
            ldsm_x4(ahi[mi][0], ahi[mi][1], ahi[mi][2], ahi[mi][3],
                    base + mi * 16 * ROWB + a_off);
            ldsm_x4(alo[mi][0], alo[mi][1], alo[mi][2], alo[mi][3],
                    base + ATILE + mi * 16 * ROWB + a_off);
        }
#pragma unroll
        for (int p = 0; p < 2; p++) {
            uint32_t r0, r1, r2, r3;
            ldsm_x4(r0, r1, r2, r3, base + 2 * ATILE + p * 16 * ROWB + b_off);
            bhi[p * 2][0] = r0; bhi[p * 2][1] = r1;
            bhi[p * 2 + 1][0] = r2; bhi[p * 2 + 1][1] = r3;
            ldsm_x4(r0, r1, r2, r3, base + 2 * ATILE + BTILE + p * 16 * ROWB + b_off);
            blo[p * 2][0] = r0; blo[p * 2][1] = r1;
            blo[p * 2 + 1][0] = r2; blo[p * 2 + 1][1] = r3;
        }

#pragma unroll
        for (int mi = 0; mi < MI; mi++)
#pragma unroll
            for (int nb = 0; nb < 4; nb++) {
                mma_bf16(acc[mi][nb], ahi[mi], bhi[nb]);
                mma_bf16(acc[mi][nb], ahi[mi], blo[nb]);
                mma_bf16(acc[mi][nb], alo[mi], bhi[nb]);
            }
    }

    const int g = lane >> 2, t = lane & 3;

    if (SPLIT_OUT) {
#pragma unroll
        for (int mi = 0; mi < MI; mi++) {
            int r0 = bm + wm + mi * 16 + g;
            int r1 = r0 + 8;
#pragma unroll
            for (int nb = 0; nb < 4; nb++) {
                int col = wn + nb * 8 + 2 * t;
                float b0 = bias[col], b1 = bias[col + 1];
#pragma unroll
                for (int rr = 0; rr < 2; rr++) {
                    int r = rr ? r1 : r0;
                    if (r < M) {
                        float v0 = acc[mi][nb][rr * 2 + 0] + b0;
                        float v1 = acc[mi][nb][rr * 2 + 1] + b1;
                        __nv_bfloat162 h2, l2;
                        h2.x = __float2bfloat16(v0); h2.y = __float2bfloat16(v1);
                        l2.x = __float2bfloat16(v0 - __bfloat162float(h2.x));
                        l2.y = __float2bfloat16(v1 - __bfloat162float(h2.y));
                        *reinterpret_cast<__nv_bfloat162*>(Ohi + (size_t)r * BN + col) = h2;
                        *reinterpret_cast<__nv_bfloat162*>(Olo + (size_t)r * BN + col) = l2;
                    }
                }
            }
        }
    } else {
#pragma unroll
        for (int mi = 0; mi < MI; mi++) {
            int r0 = bm + wm + mi * 16 + g;
            int r1 = r0 + 8;
#pragma unroll
            for (int nb = 0; nb < 4; nb++) {
                int col = bn + wn + nb * 8 + 2 * t;
                if (r0 < M)
                    *reinterpret_cast<float2*>(C + (size_t)r0 * 512 + col) =
                        make_float2(acc[mi][nb][0], acc[mi][nb][1]);
                if (r1 < M)
                    *reinterpret_cast<float2*>(C + (size_t)r1 * 512 + col) =
                        make_float2(acc[mi][nb][2], acc[mi][nb][3]);
            }
        }
        if (FUSE) {
            int hh = (bn + wn) >> 6;
            float av[4][2], rv[4][2];
#pragma unroll
            for (int nb = 0; nb < 4; nb++)
#pragma unroll
                for (int k = 0; k < 2; k++) {
                    int colh = ((bn + wn) & 63) + nb * 8 + 2 * t + k;
                    av[nb][k] = al[hh * 64 + colh];
                    rv[nb][k] = ar[hh * 64 + colh];
                }
#pragma unroll
            for (int mi = 0; mi < MI; mi++) {
                float pel0 = 0.f, per0 = 0.f, pel1 = 0.f, per1 = 0.f;
#pragma unroll
                for (int nb = 0; nb < 4; nb++) {
                    pel0 += acc[mi][nb][0] * av[nb][0] + acc[mi][nb][1] * av[nb][1];
                    per0 += acc[mi][nb][0] * rv[nb][0] + acc[mi][nb][1] * rv[nb][1];
                    pel1 += acc[mi][nb][2] * av[nb][0] + acc[mi][nb][3] * av[nb][1];
                    per1 += acc[mi][nb][2] * rv[nb][0] + acc[mi][nb][3] * rv[nb][1];
                }
#pragma unroll
                for (int off = 1; off <= 2; off <<= 1) {
                    pel0 += __shfl_xor_sync(0xffffffffu, pel0, off);
                    per0 += __shfl_xor_sync(0xffffffffu, per0, off);
                    pel1 += __shfl_xor_sync(0xffffffffu, pel1, off);
                    per1 += __shfl_xor_sync(0xffffffffu, per1, off);
                }
                if (t == 0) {
                    int r0 = bm + wm + mi * 16 + g;
                    int r1 = r0 + 8;
                    if (r0 < M) {
                        atomicAdd(&el[r0 * HEADS + hh], pel0);
                        atomicAdd(&er[r0 * HEADS + hh], per0);
                    }
                    if (r1 < M) {
                        atomicAdd(&el[r1 * HEADS + hh], pel1);
                        atomicAdd(&er[r1 * HEADS + hh], per1);
                    }
                }
            }
        }
    }
}

// ---------------- fused edge-softmax + aggregation ---------------------------
__device__ __forceinline__ float lrelu(float x) { return x > 0.f ? x : 0.2f * x; }

__global__ void k_attn(const float* __restrict__ feat, const float* __restrict__ bias,
                       const float* __restrict__ el, const float* __restrict__ er,
                       __nv_bfloat16* __restrict__ Ohi, __nv_bfloat16* __restrict__ Olo)
{
    int n = blockIdx.x;
    int h = threadIdx.y;
    int lane = threadIdx.x;
    int start = g_rowptr[n], end = g_rowptr[n + 1];
    int deg = end - start;
    float er_h = er[n * HEADS + h];

    float ax = 0.f, ay = 0.f;

    if (deg <= 32) {
        int s = 0;
        float e = -INFINITY;
        if (lane < deg) {
            s = g_csrsrc[start + lane];
            e = lrelu(el[s * HEADS + h] + er_h);
        }
        float m = e;
#pragma unroll
        for (int o = 16; o; o >>= 1) m = fmaxf(m, __shfl_xor_sync(0xffffffffu, m, o));
        float ws = (lane < deg) ? __expf(e - m) : 0.f;
        float dsum = ws;
#pragma unroll
        for (int o = 16; o; o >>= 1) dsum += __shfl_xor_sync(0xffffffffu, dsum, o);
        float w = ws / fmaxf(dsum, 1e-9f);

        int j = 0;
        for (; j + 4 <= deg; j += 4) {
            int   s0 = __shfl_sync(0xffffffffu, s, j + 0);
            int   s1 = __shfl_sync(0xffffffffu, s, j + 1);
            int   s2 = __shfl_sync(0xffffffffu, s, j + 2);
            int   s3 = __shfl_sync(0xffffffffu, s, j + 3);
            float w0 = __shfl_sync(0xffffffffu, w, j + 0);
            float w1 = __shfl_sync(0xffffffffu, w, j + 1);
            float w2 = __shfl_sync(0xffffffffu, w, j + 2);
            float w3 = __shfl_sync(0xffffffffu, w, j + 3);
            float2 v0 = *reinterpret_cast<const float2*>(feat + (size_t)s0 * 512 + h * 64 + lane * 2);
            float2 v1 = *reinterpret_cast<const float2*>(feat + (size_t)s1 * 512 + h * 64 + lane * 2);
            float2 v2 = *reinterpret_cast<const float2*>(feat + (size_t)s2 * 512 + h * 64 + lane * 2);
            float2 v3 = *reinterpret_cast<const float2*>(feat + (size_t)s3 * 512 + h * 64 + lane * 2);
            ax += w0 * v0.x + w1 * v1.x + w2 * v2.x + w3 * v3.x;
            ay += w0 * v0.y + w1 * v1.y + w2 * v2.y + w3 * v3.y;
        }
        for (; j < deg; j++) {
            int   sj = __shfl_sync(0xffffffffu, s, j);
            float wj = __shfl_sync(0xffffffffu, w, j);
            float2 v = *reinterpret_cast<const float2*>(feat + (size_t)sj * 512 + h * 64 + lane * 2);
            ax += wj * v.x; ay += wj * v.y;
        }
    } else {
        float m = -INFINITY;
        for (int j = start + lane; j < end; j += 32)
            m = fmaxf(m, lrelu(el[g_csrsrc[j] * HEADS + h] + er_h));
#pragma unroll
        for (int o = 16; o; o >>= 1) m = fmaxf(m, __shfl_xor_sync(0xffffffffu, m, o));

        float dsum = 0.f;
        for (int j = start + lane; j < end; j += 32)
            dsum += __expf(lrelu(el[g_csrsrc[j] * HEADS + h] + er_h) - m);
#pragma unroll
        for (int o = 16; o; o >>= 1) dsum += __shfl_xor_sync(0xffffffffu, dsum, o);
        float inv = 1.0f / fmaxf(dsum, 1e-9f);

        for (int j0 = start; j0 < end; j0 += 32) {
            int jmax = end - j0; if (jmax > 32) jmax = 32;
            int s_l = 0; float w_l = 0.f;
            if (lane < jmax) {
                s_l = g_csrsrc[j0 + lane];
                w_l = __expf(lrelu(el[s_l * HEADS + h] + er_h) - m) * inv;
            }
            for (int jj = 0; jj < jmax; jj++) {
                int   sj = __shfl_sync(0xffffffffu, s_l, jj);
                float wj = __shfl_sync(0xffffffffu, w_l, jj);
                float2 v = *reinterpret_cast<const float2*>(feat + (size_t)sj * 512 + h * 64 + lane * 2);
                ax += wj * v.x; ay += wj * v.y;
            }
        }
    }

    float vx = ax + bias[h * 64 + lane * 2];
    float vy = ay + bias[h * 64 + lane * 2 + 1];
    vx = vx > 0.f ? vx : (__expf(vx) - 1.f);
    vy = vy > 0.f ? vy : (__expf(vy) - 1.f);
    __nv_bfloat162 h2, l2;
    h2.x = __float2bfloat16(vx); h2.y = __float2bfloat16(vy);
    l2.x = __float2bfloat16(vx - __bfloat162float(h2.x));
    l2.y = __float2bfloat16(vy - __bfloat162float(h2.y));
    size_t o = (size_t)n * 512 + h * 64 + lane * 2;
    *reinterpret_cast<__nv_bfloat162*>(Ohi + o) = h2;
    *reinterpret_cast<__nv_bfloat162*>(Olo + o) = l2;
}

// ---------------- skinny GEMM + fused el/er (layer 2) ------------------------
__global__ __launch_bounds__(256) void k_gemm_n10(
    const __nv_bfloat16* __restrict__ Ahi, const __nv_bfloat16* __restrict__ Alo,
    const float* __restrict__ B, float* __restrict__ C,
    const float* __restrict__ al2, const float* __restrict__ ar2,
    float* __restrict__ el, float* __restrict__ er, int M)
{
    __shared__ float Bs[512 * 10];
    int tid = threadIdx.x;
    for (int i = tid; i < 512 * 10; i += 256) Bs[i] = B[i];
    __syncthreads();
    int warp = tid >> 5, lane = tid & 31;
    int row = blockIdx.x * 8 + warp;
    if (row >= M) return;
    float acc[10];
#pragma unroll
    for (int c = 0; c < 10; c++) acc[c] = 0.0f;
#pragma unroll
    for (int i = 0; i < 8; i++) {
        int k = lane * 2 + i * 64;
        __nv_bfloat162 h2 = *reinterpret_cast<const __nv_bfloat162*>(Ahi + (size_t)row * 512 + k);
        __nv_bfloat162 l2 = *reinterpret_cast<const __nv_bfloat162*>(Alo + (size_t)row * 512 + k);
        float a0 = __bfloat162float(h2.x) + __bfloat162float(l2.x);
        float a1 = __bfloat162float(h2.y) + __bfloat162float(l2.y);
#pragma unroll
        for (int c = 0; c < 10; c++)
            acc[c] += a0 * Bs[k * 10 + c] + a1 * Bs[(k + 1) * 10 + c];
    }
#pragma unroll
    for (int c = 0; c < 10; c++)
#pragma unroll
        for (int o = 16; o; o >>= 1) acc[c] += __shfl_xor_sync(0xffffffffu, acc[c], o);
    if (lane == 0) {
        float e_l = 0.f, e_r = 0.f;
#pragma unroll
        for (int c = 0; c < 10; c++) {
            C[(size_t)row * 10 + c] = acc[c];
            e_l += acc[c] * al2[c];
            e_r += acc[c] * ar2[c];
        }
        el[row] = e_l;
        er[row] = e_r;
    }
}

// ---------------- layer-2 agg (D=10, f32 out) --------------------------------
__global__ void k_agg10(const float* __restrict__ feat, const float* __restrict__ bias,
                        const float* __restrict__ el, const float* __restrict__ er,
                        float* __restrict__ out)
{
    int n = blockIdx.x;
    int lane = threadIdx.x;
    int start = g_rowptr[n], end = g_rowptr[n + 1];
    float er_h = er[n];

    float m = -INFINITY;
    for (int j = start + lane; j < end; j += 32)
        m = fmaxf(m, lrelu(el[g_csrsrc[j]] + er_h));
#pragma unroll
    for (int o = 16; o; o >>= 1) m = fmaxf(m, __shfl_xor_sync(0xffffffffu, m, o));

    float dsum = 0.f;
    for (int j = start + lane; j < end; j += 32)
        dsum += __expf(lrelu(el[g_csrsrc[j]] + er_h) - m);
#pragma unroll
    for (int o = 16; o; o >>= 1) dsum += __shfl_xor_sync(0xffffffffu, dsum, o);
    float inv = 1.0f / fmaxf(dsum, 1e-9f);

    float acc = 0.f;
    for (int j0 = start; j0 < end; j0 += 32) {
        int jmax = end - j0; if (jmax > 32) jmax = 32;
        int s_l = 0; float w_l = 0.f;
        if (lane < jmax) {
            s_l = g_csrsrc[j0 + lane];
            w_l = __expf(lrelu(el[s_l] + er_h) - m);
        }
        for (int jj = 0; jj < jmax; jj++) {
            int   s = __shfl_sync(0xffffffffu, s_l, jj);
            float w = __shfl_sync(0xffffffffu, w_l, jj);
            if (lane < NCLS) acc += w * feat[(size_t)s * NCLS + lane];
        }
    }
    if (lane < NCLS) out[(size_t)n * NCLS + lane] = acc * inv + bias[lane];
}

// ---------------- launcher ----------------------------------------------------
extern "C" void kernel_launch(void* const* d_in, const int* in_sizes, int n_in,
                              void* d_out, int out_size)
{
    const float* feat0 = (const float*)d_in[0];
    const float* feat1 = (const float*)d_in[1];
    const float* fc0w  = (const float*)d_in[2];
    const float* fc0b  = (const float*)d_in[3];
    const float* fc1w  = (const float*)d_in[4];
    const float* fc1b  = (const float*)d_in[5];
    const float* W0    = (const float*)d_in[6];
    const float* al0   = (const float*)d_in[7];
    const float* ar0   = (const float*)d_in[8];
    const float* b0    = (const float*)d_in[9];
    const float* W1    = (const float*)d_in[10];
    const float* al1   = (const float*)d_in[11];
    const float* ar1   = (const float*)d_in[12];
    const float* b1    = (const float*)d_in[13];
    const float* W2    = (const float*)d_in[14];
    const float* al2   = (const float*)d_in[15];
    const float* ar2   = (const float*)d_in[16];
    const float* b2    = (const float*)d_in[17];
    const int*   ei    = (const int*)d_in[18];

    const int E = in_sizes[18] / 2;
    const int M0 = in_sizes[0] / 256;   // 30000
    const int M1 = in_sizes[1] / 128;   // 20000
    const int* src = ei;
    const int* dst = ei + E;

    float *bufA, *bufB, *elA, *erA, *elB, *erB;
    __nv_bfloat16 *fhi, *flo, *hhi, *hlo, *ahi, *alo;
    __nv_bfloat16 *wf0h, *wf0l, *wf1h, *wf1l, *w0th, *w0tl, *w1th, *w1tl;
    cudaGetSymbolAddress((void**)&bufA, g_bufA);
    cudaGetSymbolAddress((void**)&bufB, g_bufB);
    cudaGetSymbolAddress((void**)&elA,  g_elA);
    cudaGetSymbolAddress((void**)&erA,  g_erA);
    cudaGetSymbolAddress((void**)&elB,  g_elB);
    cudaGetSymbolAddress((void**)&erB,  g_erB);
    cudaGetSymbolAddress((void**)&fhi,  g_f_hi);
    cudaGetSymbolAddress((void**)&flo,  g_f_lo);
    cudaGetSymbolAddress((void**)&hhi,  g_h_hi);
    cudaGetSymbolAddress((void**)&hlo,  g_h_lo);
    cudaGetSymbolAddress((void**)&ahi,  g_a_hi);
    cudaGetSymbolAddress((void**)&alo,  g_a_lo);
    cudaGetSymbolAddress((void**)&wf0h, g_wf0_hi);
    cudaGetSymbolAddress((void**)&wf0l, g_wf0_lo);
    cudaGetSymbolAddress((void**)&wf1h, g_wf1_hi);
    cudaGetSymbolAddress((void**)&wf1l, g_wf1_lo);
    cudaGetSymbolAddress((void**)&w0th, g_w0t_hi);
    cudaGetSymbolAddress((void**)&w0tl, g_w0t_lo);
    cudaGetSymbolAddress((void**)&w1th, g_w1t_hi);
    cudaGetSymbolAddress((void**)&w1tl, g_w1t_lo);

    float* outp = (float*)d_out;

    constexpr int SMEM_MM = STG * 18432;   // 73728 for all variants
    cudaFuncSetAttribute((const void*)&k_mma<256, 128, 64, false, true>,
                         cudaFuncAttributeMaxDynamicSharedMemorySize, SMEM_MM);
    cudaFuncSetAttribute((const void*)&k_mma<128, 128, 64, false, true>,
                         cudaFuncAttributeMaxDynamicSharedMemorySize, SMEM_MM);
    cudaFuncSetAttribute((const void*)&k_mma<64, 64, 128, true, false>,
                         cudaFuncAttributeMaxDynamicSharedMemorySize, SMEM_MM);
    cudaFuncSetAttribute((const void*)&k_mma<512, 64, 128, true, false>,
                         cudaFuncAttributeMaxDynamicSharedMemorySize, SMEM_MM);

    // fork side streams off the (possibly capturing) default stream
    cudaStream_t sB, sC;
    cudaStreamCreateWithFlags(&sB, cudaStreamNonBlocking);
    cudaStreamCreateWithFlags(&sC, cudaStreamNonBlocking);
    cudaEvent_t evFork, evB, evC;
    cudaEventCreateWithFlags(&evFork, cudaEventDisableTiming);
    cudaEventCreateWithFlags(&evB,    cudaEventDisableTiming);
    cudaEventCreateWithFlags(&evC,    cudaEventDisableTiming);
    cudaEventRecord(evFork, 0);
    cudaStreamWaitEvent(sB, evFork, 0);
    cudaStreamWaitEvent(sC, evFork, 0);

    // main stream, launches 0..3 (index 3 = profiled proj0 mma)
    k_asplit<<<(M0 * 256 / 4 + 255) / 256, 256>>>(feat0, fhi, flo, M0 * 256);
    k_asplit<<<(M1 * 128 / 4 + 255) / 256, 256>>>(feat1, fhi + F0SZ, flo + F0SZ, M1 * 128);
    k_tsplit<<<dim3(2, 8),  dim3(32, 32)>>>(fc0w, wf0h, wf0l, 256, 64);
    k_mma<256, 128, 64, false, true><<<dim3(1, 235), 256, SMEM_MM>>>(
        fhi, flo, wf0h, wf0l, nullptr, hhi, hlo, fc0b,
        nullptr, nullptr, nullptr, nullptr, M0);

    // side stream B: CSR build
    k_zero_deg<<<(NN + 255) / 256, 256, 0, sB>>>();
    k_count<<<(E + 255) / 256, 256, 0, sB>>>(dst, E);
    k_scan1<<<NBLK, 256, 0, sB>>>();
    k_scan2<<<1, 256, 0, sB>>>();
    k_scan3<<<NBLK, 256, 0, sB>>>();
    k_scatter<<<(E + 255) / 256, 256, 0, sB>>>(src, dst, E);
    cudaEventRecord(evB, sB);

    // side stream C: layer weight splits + el/er zero
    k_zero_el<<<(NN * HEADS + 255) / 256, 256, 0, sC>>>();
    k_tsplit<<<dim3(16, 2),  dim3(32, 32), 0, sC>>>(W0, w0th, w0tl, 64, 512);
    k_tsplit<<<dim3(16, 16), dim3(32, 32), 0, sC>>>(W1, w1th, w1tl, 512, 512);
    cudaEventRecord(evC, sC);

    // main stream continues: proj1
    k_tsplit<<<dim3(2, 4), dim3(32, 32)>>>(fc1w, wf1h, wf1l, 128, 64);
    k_mma<128, 128, 64, false, true><<<dim3(1, 157), 256, SMEM_MM>>>(
        fhi + F0SZ, flo + F0SZ, wf1h, wf1l, nullptr,
        hhi + (size_t)M0 * 64, hlo + (size_t)M0 * 64, fc1b,
        nullptr, nullptr, nullptr, nullptr, M1);

    // join C (W0/W1 splits + zeros) before layer-0 mma
    cudaStreamWaitEvent(0, evC, 0);
    k_mma<64, 64, 128, true, false><<<dim3(4, 782), 256, SMEM_MM>>>(
        hhi, hlo, w0th, w0tl, bufA, nullptr, nullptr, nullptr,
        al0, ar0, elA, erA, NN);

    // join B (CSR) before attention
    cudaStreamWaitEvent(0, evB, 0);
    k_attn<<<NN, dim3(32, HEADS)>>>(bufA, b0, elA, erA, ahi, alo);

    // layer 1
    k_mma<512, 64, 128, true, false><<<dim3(4, 782), 256, SMEM_MM>>>(
        ahi, alo, w1th, w1tl, bufA, nullptr, nullptr, nullptr,
        al1, ar1, elB, erB, NN);
    k_attn<<<NN, dim3(32, HEADS)>>>(bufA, b1, elB, erB, ahi, alo);

    // layer 2
    k_gemm_n10<<<(NN + 7) / 8, 256>>>(ahi, alo, W2, bufB, al2, ar2, elA, erA, NN);
    k_agg10<<<NN, 32>>>(bufB, b2, elA, erA, outp);

    cudaEventDestroy(evFork);
    cudaEventDestroy(evB);
    cudaEventDestroy(evC);
    cudaStreamDestroy(sB);
    cudaStreamDestroy(sC);

    (void)n_in; (void)out_size;
}

// round 9
// speedup vs baseline: 1.0616x; 1.0616x over previous
#include <cuda_runtime.h>
#include <cuda_bf16.h>
#include <math.h>
#include <stdint.h>

#define NN 50000
#define NE 500000
#define HID 64
#define HEADS 8
#define NCLS 10
#define MPAD 50048            // 391 * 128
#define F0ROWS 30080          // 235*128
#define F1ROWS 20096          // 157*128
#define F0SZ (F0ROWS * 256)
#define FSZ  (F0SZ + F1ROWS * 128)
#define NBLK 196              // scan blocks: 196*256 = 50176 >= NN

// ---------------- scratch -----------------------------------------------
__device__ float g_bufA[(size_t)NN * 512];
__device__ float g_bufB[(size_t)NN * 512];
__device__ float g_elA[NN * HEADS];
__device__ float g_erA[NN * HEADS];
__device__ float g_elB[NN * HEADS];
__device__ float g_erB[NN * HEADS];
__device__ int   g_deg[NN];
__device__ int   g_rowptr[NN + 1];
__device__ int   g_cursor[NN];
__device__ int   g_csrsrc[NE];
__device__ int   g_blksum[256];
__device__ int   g_blkoff[256];
__device__ __nv_bfloat16 g_f_hi[FSZ];
__device__ __nv_bfloat16 g_f_lo[FSZ];
__device__ __nv_bfloat16 g_h_hi[(size_t)MPAD * 64];
__device__ __nv_bfloat16 g_h_lo[(size_t)MPAD * 64];
__device__ __nv_bfloat16 g_a_hi[(size_t)MPAD * 512];
__device__ __nv_bfloat16 g_a_lo[(size_t)MPAD * 512];
__device__ __nv_bfloat16 g_wf0_hi[64 * 256], g_wf0_lo[64 * 256];
__device__ __nv_bfloat16 g_wf1_hi[64 * 128], g_wf1_lo[64 * 128];
__device__ __nv_bfloat16 g_w0t_hi[512 * 64], g_w0t_lo[512 * 64];
__device__ __nv_bfloat16 g_w1t_hi[512 * 512], g_w1t_lo[512 * 512];

// ---------------- PTX helpers --------------------------------------------
__device__ __forceinline__ uint32_t smem_u32(const void* p) {
    uint32_t a;
    asm("{ .reg .u64 t; cvta.to.shared.u64 t, %1; cvt.u32.u64 %0, t; }" : "=r"(a) : "l"(p));
    return a;
}
__device__ __forceinline__ void cp_async16(uint32_t s, const void* g) {
    asm volatile("cp.async.cg.shared.global [%0], [%1], 16;" :: "r"(s), "l"(g));
}
#define CP_COMMIT() asm volatile("cp.async.commit_group;" ::: "memory")

__device__ __forceinline__ void ldsm_x4(uint32_t& r0, uint32_t& r1, uint32_t& r2, uint32_t& r3,
                                        uint32_t addr) {
    asm volatile("ldmatrix.sync.aligned.m8n8.x4.shared.b16 {%0,%1,%2,%3}, [%4];"
                 : "=r"(r0), "=r"(r1), "=r"(r2), "=r"(r3) : "r"(addr));
}
__device__ __forceinline__ void mma_bf16(float* d, const uint32_t* a, const uint32_t* b) {
    asm volatile(
        "mma.sync.aligned.m16n8k16.row.col.f32.bf16.bf16.f32 "
        "{%0,%1,%2,%3}, {%4,%5,%6,%7}, {%8,%9}, {%0,%1,%2,%3};"
        : "+f"(d[0]), "+f"(d[1]), "+f"(d[2]), "+f"(d[3])
        : "r"(a[0]), "r"(a[1]), "r"(a[2]), "r"(a[3]), "r"(b[0]), "r"(b[1]));
}

// ---------------- graph preprocessing ---------------------------------------
__global__ void k_zero_deg() {
    int i = blockIdx.x * blockDim.x + threadIdx.x;
    if (i < NN) g_deg[i] = 0;
}
__global__ void k_zero_el() {
    int i = blockIdx.x * blockDim.x + threadIdx.x;
    if (i < NN * HEADS) {
        g_elA[i] = 0.f; g_erA[i] = 0.f;
        g_elB[i] = 0.f; g_erB[i] = 0.f;
    }
}
__global__ void k_count(const int* __restrict__ dst, int E) {
    int e = blockIdx.x * blockDim.x + threadIdx.x;
    if (e < E) atomicAdd(&g_deg[dst[e]], 1);
}
__global__ void k_scan1() {
    __shared__ int sh[256];
    int b = blockIdx.x, t = threadIdx.x;
    int i = b * 256 + t;
    int v = (i < NN) ? g_deg[i] : 0;
    sh[t] = v;
    __syncthreads();
#pragma unroll
    for (int off = 1; off < 256; off <<= 1) {
        int x = (t >= off) ? sh[t - off] : 0;
        __syncthreads();
        sh[t] += x;
        __syncthreads();
    }
    if (i < NN) g_rowptr[i] = sh[t] - v;
    if (t == 255) g_blksum[b] = sh[255];
}
__global__ void k_scan2() {
    __shared__ int sh[256];
    int t = threadIdx.x;
    int v = (t < NBLK) ? g_blksum[t] : 0;
    sh[t] = v;
    __syncthreads();
#pragma unroll
    for (int off = 1; off < 256; off <<= 1) {
        int x = (t >= off) ? sh[t - off] : 0;
        __syncthreads();
        sh[t] += x;
        __syncthreads();
    }
    if (t < NBLK) g_blkoff[t] = sh[t] - v;
    if (t == 255) g_rowptr[NN] = sh[255];
}
__global__ void k_scan3() {
    int i = blockIdx.x * blockDim.x + threadIdx.x;
    if (i < NN) {
        int r = g_rowptr[i] + g_blkoff[i >> 8];
        g_rowptr[i] = r;
        g_cursor[i] = r;
    }
}
__global__ void k_scatter(const int* __restrict__ src, const int* __restrict__ dst, int E) {
    int e = blockIdx.x * blockDim.x + threadIdx.x;
    if (e < E) {
        int pos = atomicAdd(&g_cursor[dst[e]], 1);
        g_csrsrc[pos] = src[e];
    }
}

// ---------------- weight transpose + bf16 split -----------------------------
__global__ void k_tsplit(const float* __restrict__ W, __nv_bfloat16* __restrict__ Thi,
                         __nv_bfloat16* __restrict__ Tlo, int K, int N)
{
    __shared__ float s[32][33];
    int tx = threadIdx.x, ty = threadIdx.y;
    int k = blockIdx.y * 32 + ty, n = blockIdx.x * 32 + tx;
    s[ty][tx] = W[(size_t)k * N + n];
    __syncthreads();
    int n2 = blockIdx.x * 32 + ty, k2 = blockIdx.y * 32 + tx;
    float v = s[tx][ty];
    __nv_bfloat16 h = __float2bfloat16(v);
    Thi[(size_t)n2 * K + k2] = h;
    Tlo[(size_t)n2 * K + k2] = __float2bfloat16(v - __bfloat162float(h));
}

__global__ void k_asplit(const float* __restrict__ A, __nv_bfloat16* __restrict__ hi,
                         __nv_bfloat16* __restrict__ lo, int count)
{
    int i = (blockIdx.x * blockDim.x + threadIdx.x) * 4;
    if (i >= count) return;
    float4 v = *reinterpret_cast<const float4*>(A + i);
    __nv_bfloat162 h0, h1, l0, l1;
    h0.x = __float2bfloat16(v.x); h0.y = __float2bfloat16(v.y);
    h1.x = __float2bfloat16(v.z); h1.y = __float2bfloat16(v.w);
    l0.x = __float2bfloat16(v.x - __bfloat162float(h0.x));
    l0.y = __float2bfloat16(v.y - __bfloat162float(h0.y));
    l1.x = __float2bfloat16(v.z - __bfloat162float(h1.x));
    l1.y = __float2bfloat16(v.w - __bfloat162float(h1.y));
    *reinterpret_cast<__nv_bfloat162*>(hi + i) = h0;
    *reinterpret_cast<__nv_bfloat162*>(hi + i + 2) = h1;
    *reinterpret_cast<__nv_bfloat162*>(lo + i) = l0;
    *reinterpret_cast<__nv_bfloat162*>(lo + i + 2) = l1;
}

// ---------------- generalized bf16 3x-split mma GEMM -------------------------
// 4-stage cp.async pipeline, ONE __syncthreads per K chunk.
// MMA inner loop split into 3 dependency-free passes (hh / hl / lh).
#define ROWB 48
#define TILEB (128 * ROWB)
#define STG 4
template <int KDIM, int BN, bool FUSE, bool SPLIT_OUT>
__global__ __launch_bounds__(256) void k_mma(
    const __nv_bfloat16* __restrict__ Ahi, const __nv_bfloat16* __restrict__ Alo,
    const __nv_bfloat16* __restrict__ Bhi, const __nv_bfloat16* __restrict__ Blo,
    float* __restrict__ C,
    __nv_bfloat16* __restrict__ Ohi, __nv_bfloat16* __restrict__ Olo,
    const float* __restrict__ bias,
    const float* __restrict__ al, const float* __restrict__ ar,
    float* __restrict__ el, float* __restrict__ er,
    int M)
{
    constexpr int NCH = KDIM / 16;
    constexpr int MI = (BN == 128) ? 4 : 2;
    constexpr int BTILE = BN * ROWB;
    constexpr int BUFB = 2 * TILEB + 2 * BTILE;
    extern __shared__ char smem[];
    uint32_t sb = smem_u32(smem);

    const int tid = threadIdx.x;
    const int wid = tid >> 5, lane = tid & 31;
    const int bm = blockIdx.y * 128;
    const int bn = blockIdx.x * BN;
    const int wm = (BN == 128) ? (wid & 1) * 64 : (wid & 3) * 32;
    const int wn = (BN == 128) ? (wid >> 1) * 32 : (wid >> 2) * 32;

    const int lrow = tid >> 1, lhalf = tid & 1;
    const bool bOK = (BN == 128) || (tid < 128);
    const __nv_bfloat16* gAh = Ahi + (size_t)(bm + lrow) * KDIM + lhalf * 8;
    const __nv_bfloat16* gAl = Alo + (size_t)(bm + lrow) * KDIM + lhalf * 8;
    const int brow = bOK ? lrow : 0;
    const __nv_bfloat16* gBh = Bhi + (size_t)(bn + brow) * KDIM + lhalf * 8;
    const __nv_bfloat16* gBl = Blo + (size_t)(bn + brow) * KDIM + lhalf * 8;
    const uint32_t sdst = lrow * ROWB + lhalf * 16;
    const uint32_t sdstB = brow * ROWB + lhalf * 16;

    auto load_chunk = [&](int c) {
        uint32_t base = sb + (c % STG) * BUFB;
        int k0 = c * 16;
        cp_async16(base + sdst,         gAh + k0);
        cp_async16(base + TILEB + sdst, gAl + k0);
        if (bOK) {
            cp_async16(base + 2 * TILEB + sdstB,         gBh + k0);
            cp_async16(base + 2 * TILEB + BTILE + sdstB, gBl + k0);
        }
    };

    float acc[MI][4][4];
#pragma unroll
    for (int i = 0; i < MI; i++)
#pragma unroll
        for (int j = 0; j < 4; j++)
#pragma unroll
            for (int k = 0; k < 4; k++) acc[i][j][k] = 0.f;

    // prologue: fill STG-1 stages
#pragma unroll
    for (int c = 0; c < STG - 1 && c < NCH; c++) {
        load_chunk(c);
        CP_COMMIT();
    }

    const uint32_t a_off = (wm + (lane & 15)) * ROWB + (lane >> 4) * 16;
    const uint32_t b_off = (wn + (lane & 7) + ((lane >> 4) << 3)) * ROWB + (((lane >> 3) & 1) * 16);

    for (int c = 0; c < NCH; c++) {
        const uint32_t base = sb + (c % STG) * BUFB;
        asm volatile("cp.async.wait_group %0;" :: "n"(STG - 2));
        __syncthreads();

        if (c + STG - 1 < NCH) load_chunk(c + STG - 1);
        CP_COMMIT();

        uint32_t ahi[MI][4], alo[MI][4], bhi[4][2], blo[4][2];
#pragma unroll
        for (int mi = 0; mi < MI; mi++) {
            ldsm_x4(ahi[mi][0], ahi[mi][1], ahi[mi][2], ahi[mi][3],
                    base + mi * 16 * ROWB + a_off);
            ldsm_x4(alo[mi][0], alo[mi][1], alo[mi][2], alo[mi][3],
                    base + TILEB + mi * 16 * ROWB + a_off);
        }
#pragma unroll
        for (int p = 0; p < 2; p++) {
            uint32_t r0, r1, r2, r3;
            ldsm_x4(r0, r1, r2, r3, base + 2 * TILEB + p * 16 * ROWB + b_off);
            bhi[p * 2][0] = r0; bhi[p * 2][1] = r1;
            bhi[p * 2 + 1][0] = r2; bhi[p * 2 + 1][1] = r3;
            ldsm_x4(r0, r1, r2, r3, base + 2 * TILEB + BTILE + p * 16 * ROWB + b_off);
            blo[p * 2][0] = r0; blo[p * 2][1] = r1;
            blo[p * 2 + 1][0] = r2; blo[p * 2 + 1][1] = r3;
        }

        // pass 1: hh — all accumulators independent
#pragma unroll
        for (int mi = 0; mi < MI; mi++)
#pragma unroll
            for (int nb = 0; nb < 4; nb++)
                mma_bf16(acc[mi][nb], ahi[mi], bhi[nb]);
        // pass 2: hl
#pragma unroll
        for (int mi = 0; mi < MI; mi++)
#pragma unroll
            for (int nb = 0; nb < 4; nb++)
                mma_bf16(acc[mi][nb], ahi[mi], blo[nb]);
        // pass 3: lh
#pragma unroll
        for (int mi = 0; mi < MI; mi++)
#pragma unroll
            for (int nb = 0; nb < 4; nb++)
                mma_bf16(acc[mi][nb], alo[mi], bhi[nb]);
    }

    const int g = lane >> 2, t = lane & 3;

    if (SPLIT_OUT) {
#pragma unroll
        for (int mi = 0; mi < MI; mi++) {
            int r0 = bm + wm + mi * 16 + g;
            int r1 = r0 + 8;
#pragma unroll
            for (int nb = 0; nb < 4; nb++) {
                int col = wn + nb * 8 + 2 * t;
                float b0 = bias[col], b1 = bias[col + 1];
#pragma unroll
                for (int rr = 0; rr < 2; rr++) {
                    int r = rr ? r1 : r0;
                    if (r < M) {
                        float v0 = acc[mi][nb][rr * 2 + 0] + b0;
                        float v1 = acc[mi][nb][rr * 2 + 1] + b1;
                        __nv_bfloat162 h2, l2;
                        h2.x = __float2bfloat16(v0); h2.y = __float2bfloat16(v1);
                        l2.x = __float2bfloat16(v0 - __bfloat162float(h2.x));
                        l2.y = __float2bfloat16(v1 - __bfloat162float(h2.y));
                        *reinterpret_cast<__nv_bfloat162*>(Ohi + (size_t)r * BN + col) = h2;
                        *reinterpret_cast<__nv_bfloat162*>(Olo + (size_t)r * BN + col) = l2;
                    }
                }
            }
        }
    } else {
#pragma unroll
        for (int mi = 0; mi < MI; mi++) {
            int r0 = bm + wm + mi * 16 + g;
            int r1 = r0 + 8;
#pragma unroll
            for (int nb = 0; nb < 4; nb++) {
                int col = bn + wn + nb * 8 + 2 * t;
                if (r0 < M)
                    *reinterpret_cast<float2*>(C + (size_t)r0 * 512 + col) =
                        make_float2(acc[mi][nb][0], acc[mi][nb][1]);
                if (r1 < M)
                    *reinterpret_cast<float2*>(C + (size_t)r1 * 512 + col) =
                        make_float2(acc[mi][nb][2], acc[mi][nb][3]);
            }
        }
        if (FUSE) {
            int hh = (bn + wn) >> 6;
            float av[4][2], rv[4][2];
#pragma unroll
            for (int nb = 0; nb < 4; nb++)
#pragma unroll
                for (int k = 0; k < 2; k++) {
                    int colh = (wn & 63) + nb * 8 + 2 * t + k;
                    av[nb][k] = al[hh * 64 + colh];
                    rv[nb][k] = ar[hh * 64 + colh];
                }
#pragma unroll
            for (int mi = 0; mi < MI; mi++) {
                float pel0 = 0.f, per0 = 0.f, pel1 = 0.f, per1 = 0.f;
#pragma unroll
                for (int nb = 0; nb < 4; nb++) {
                    pel0 += acc[mi][nb][0] * av[nb][0] + acc[mi][nb][1] * av[nb][1];
                    per0 += acc[mi][nb][0] * rv[nb][0] + acc[mi][nb][1] * rv[nb][1];
                    pel1 += acc[mi][nb][2] * av[nb][0] + acc[mi][nb][3] * av[nb][1];
                    per1 += acc[mi][nb][2] * rv[nb][0] + acc[mi][nb][3] * rv[nb][1];
                }
#pragma unroll
                for (int off = 1; off <= 2; off <<= 1) {
                    pel0 += __shfl_xor_sync(0xffffffffu, pel0, off);
                    per0 += __shfl_xor_sync(0xffffffffu, per0, off);
                    pel1 += __shfl_xor_sync(0xffffffffu, pel1, off);
                    per1 += __shfl_xor_sync(0xffffffffu, per1, off);
                }
                if (t == 0) {
                    int r0 = bm + wm + mi * 16 + g;
                    int r1 = r0 + 8;
                    if (r0 < M) {
                        atomicAdd(&el[r0 * HEADS + hh], pel0);
                        atomicAdd(&er[r0 * HEADS + hh], per0);
                    }
                    if (r1 < M) {
                        atomicAdd(&el[r1 * HEADS + hh], pel1);
                        atomicAdd(&er[r1 * HEADS + hh], per1);
                    }
                }
            }
        }
    }
}

// ---------------- fused edge-softmax + aggregation ---------------------------
__device__ __forceinline__ float lrelu(float x) { return x > 0.f ? x : 0.2f * x; }

__global__ void k_attn(const float* __restrict__ feat, const float* __restrict__ bias,
                       const float* __restrict__ el, const float* __restrict__ er,
                       __nv_bfloat16* __restrict__ Ohi, __nv_bfloat16* __restrict__ Olo)
{
    int n = blockIdx.x;
    int h = threadIdx.y;
    int lane = threadIdx.x;
    int start = g_rowptr[n], end = g_rowptr[n + 1];
    int deg = end - start;
    float er_h = er[n * HEADS + h];

    float ax = 0.f, ay = 0.f;

    if (deg <= 32) {
        int s = 0;
        float e = -INFINITY;
        if (lane < deg) {
            s = g_csrsrc[start + lane];
            e = lrelu(el[s * HEADS + h] + er_h);
        }
        float m = e;
#pragma unroll
        for (int o = 16; o; o >>= 1) m = fmaxf(m, __shfl_xor_sync(0xffffffffu, m, o));
        float ws = (lane < deg) ? __expf(e - m) : 0.f;
        float dsum = ws;
#pragma unroll
        for (int o = 16; o; o >>= 1) dsum += __shfl_xor_sync(0xffffffffu, dsum, o);
        float w = ws / fmaxf(dsum, 1e-9f);

        int j = 0;
        for (; j + 4 <= deg; j += 4) {
            int   s0 = __shfl_sync(0xffffffffu, s, j + 0);
            int   s1 = __shfl_sync(0xffffffffu, s, j + 1);
            int   s2 = __shfl_sync(0xffffffffu, s, j + 2);
            int   s3 = __shfl_sync(0xffffffffu, s, j + 3);
            float w0 = __shfl_sync(0xffffffffu, w, j + 0);
            float w1 = __shfl_sync(0xffffffffu, w, j + 1);
            float w2 = __shfl_sync(0xffffffffu, w, j + 2);
            float w3 = __shfl_sync(0xffffffffu, w, j + 3);
            float2 v0 = *reinterpret_cast<const float2*>(feat + (size_t)s0 * 512 + h * 64 + lane * 2);
            float2 v1 = *reinterpret_cast<const float2*>(feat + (size_t)s1 * 512 + h * 64 + lane * 2);
            float2 v2 = *reinterpret_cast<const float2*>(feat + (size_t)s2 * 512 + h * 64 + lane * 2);
            float2 v3 = *reinterpret_cast<const float2*>(feat + (size_t)s3 * 512 + h * 64 + lane * 2);
            ax += w0 * v0.x + w1 * v1.x + w2 * v2.x + w3 * v3.x;
            ay += w0 * v0.y + w1 * v1.y + w2 * v2.y + w3 * v3.y;
        }
        for (; j < deg; j++) {
            int   sj = __shfl_sync(0xffffffffu, s, j);
            float wj = __shfl_sync(0xffffffffu, w, j);
            float2 v = *reinterpret_cast<const float2*>(feat + (size_t)sj * 512 + h * 64 + lane * 2);
            ax += wj * v.x; ay += wj * v.y;
        }
    } else {
        float m = -INFINITY;
        for (int j = start + lane; j < end; j += 32)
            m = fmaxf(m, lrelu(el[g_csrsrc[j] * HEADS + h] + er_h));
#pragma unroll
        for (int o = 16; o; o >>= 1) m = fmaxf(m, __shfl_xor_sync(0xffffffffu, m, o));

        float dsum = 0.f;
        for (int j = start + lane; j < end; j += 32)
            dsum += __expf(lrelu(el[g_csrsrc[j] * HEADS + h] + er_h) - m);
#pragma unroll
        for (int o = 16; o; o >>= 1) dsum += __shfl_xor_sync(0xffffffffu, dsum, o);
        float inv = 1.0f / fmaxf(dsum, 1e-9f);

        for (int j0 = start; j0 < end; j0 += 32) {
            int jmax = end - j0; if (jmax > 32) jmax = 32;
            int s_l = 0; float w_l = 0.f;
            if (lane < jmax) {
                s_l = g_csrsrc[j0 + lane];
                w_l = __expf(lrelu(el[s_l * HEADS + h] + er_h) - m) * inv;
            }
            for (int jj = 0; jj < jmax; jj++) {
                int   sj = __shfl_sync(0xffffffffu, s_l, jj);
                float wj = __shfl_sync(0xffffffffu, w_l, jj);
                float2 v = *reinterpret_cast<const float2*>(feat + (size_t)sj * 512 + h * 64 + lane * 2);
                ax += wj * v.x; ay += wj * v.y;
            }
        }
    }

    float vx = ax + bias[h * 64 + lane * 2];
    float vy = ay + bias[h * 64 + lane * 2 + 1];
    vx = vx > 0.f ? vx : (__expf(vx) - 1.f);
    vy = vy > 0.f ? vy : (__expf(vy) - 1.f);
    __nv_bfloat162 h2, l2;
    h2.x = __float2bfloat16(vx); h2.y = __float2bfloat16(vy);
    l2.x = __float2bfloat16(vx - __bfloat162float(h2.x));
    l2.y = __float2bfloat16(vy - __bfloat162float(h2.y));
    size_t o = (size_t)n * 512 + h * 64 + lane * 2;
    *reinterpret_cast<__nv_bfloat162*>(Ohi + o) = h2;
    *reinterpret_cast<__nv_bfloat162*>(Olo + o) = l2;
}

// ---------------- skinny GEMM + fused el/er (layer 2) ------------------------
__global__ __launch_bounds__(256) void k_gemm_n10(
    const __nv_bfloat16* __restrict__ Ahi, const __nv_bfloat16* __restrict__ Alo,
    const float* __restrict__ B, float* __restrict__ C,
    const float* __restrict__ al2, const float* __restrict__ ar2,
    float* __restrict__ el, float* __restrict__ er, int M)
{
    __shared__ float Bs[512 * 10];
    int tid = threadIdx.x;
    for (int i = tid; i < 512 * 10; i += 256) Bs[i] = B[i];
    __syncthreads();
    int warp = tid >> 5, lane = tid & 31;
    int row = blockIdx.x * 8 + warp;
    if (row >= M) return;
    float acc[10];
#pragma unroll
    for (int c = 0; c < 10; c++) acc[c] = 0.0f;
#pragma unroll
    for (int i = 0; i < 8; i++) {
        int k = lane * 2 + i * 64;
        __nv_bfloat162 h2 = *reinterpret_cast<const __nv_bfloat162*>(Ahi + (size_t)row * 512 + k);
        __nv_bfloat162 l2 = *reinterpret_cast<const __nv_bfloat162*>(Alo + (size_t)row * 512 + k);
        float a0 = __bfloat162float(h2.x) + __bfloat162float(l2.x);
        float a1 = __bfloat162float(h2.y) + __bfloat162float(l2.y);
#pragma unroll
        for (int c = 0; c < 10; c++)
            acc[c] += a0 * Bs[k * 10 + c] + a1 * Bs[(k + 1) * 10 + c];
    }
#pragma unroll
    for (int c = 0; c < 10; c++)
#pragma unroll
        for (int o = 16; o; o >>= 1) acc[c] += __shfl_xor_sync(0xffffffffu, acc[c], o);
    if (lane == 0) {
        float e_l = 0.f, e_r = 0.f;
#pragma unroll
        for (int c = 0; c < 10; c++) {
            C[(size_t)row * 10 + c] = acc[c];
            e_l += acc[c] * al2[c];
            e_r += acc[c] * ar2[c];
        }
        el[row] = e_l;
        er[row] = e_r;
    }
}

// ---------------- layer-2 agg (D=10, f32 out) --------------------------------
__global__ void k_agg10(const float* __restrict__ feat, const float* __restrict__ bias,
                        const float* __restrict__ el, const float* __restrict__ er,
                        float* __restrict__ out)
{
    int n = blockIdx.x;
    int lane = threadIdx.x;
    int start = g_rowptr[n], end = g_rowptr[n + 1];
    float er_h = er[n];

    float m = -INFINITY;
    for (int j = start + lane; j < end; j += 32)
        m = fmaxf(m, lrelu(el[g_csrsrc[j]] + er_h));
#pragma unroll
    for (int o = 16; o; o >>= 1) m = fmaxf(m, __shfl_xor_sync(0xffffffffu, m, o));

    float dsum = 0.f;
    for (int j = start + lane; j < end; j += 32)
        dsum += __expf(lrelu(el[g_csrsrc[j]] + er_h) - m);
#pragma unroll
    for (int o = 16; o; o >>= 1) dsum += __shfl_xor_sync(0xffffffffu, dsum, o);
    float inv = 1.0f / fmaxf(dsum, 1e-9f);

    float acc = 0.f;
    for (int j0 = start; j0 < end; j0 += 32) {
        int jmax = end - j0; if (jmax > 32) jmax = 32;
        int s_l = 0; float w_l = 0.f;
        if (lane < jmax) {
            s_l = g_csrsrc[j0 + lane];
            w_l = __expf(lrelu(el[s_l] + er_h) - m);
        }
        for (int jj = 0; jj < jmax; jj++) {
            int   s = __shfl_sync(0xffffffffu, s_l, jj);
            float w = __shfl_sync(0xffffffffu, w_l, jj);
            if (lane < NCLS) acc += w * feat[(size_t)s * NCLS + lane];
        }
    }
    if (lane < NCLS) out[(size_t)n * NCLS + lane] = acc * inv + bias[lane];
}

// ---------------- launcher ----------------------------------------------------
extern "C" void kernel_launch(void* const* d_in, const int* in_sizes, int n_in,
                              void* d_out, int out_size)
{
    const float* feat0 = (const float*)d_in[0];
    const float* feat1 = (const float*)d_in[1];
    const float* fc0w  = (const float*)d_in[2];
    const float* fc0b  = (const float*)d_in[3];
    const float* fc1w  = (const float*)d_in[4];
    const float* fc1b  = (const float*)d_in[5];
    const float* W0    = (const float*)d_in[6];
    const float* al0   = (const float*)d_in[7];
    const float* ar0   = (const float*)d_in[8];
    const float* b0    = (const float*)d_in[9];
    const float* W1    = (const float*)d_in[10];
    const float* al1   = (const float*)d_in[11];
    const float* ar1   = (const float*)d_in[12];
    const float* b1    = (const float*)d_in[13];
    const float* W2    = (const float*)d_in[14];
    const float* al2   = (const float*)d_in[15];
    const float* ar2   = (const float*)d_in[16];
    const float* b2    = (const float*)d_in[17];
    const int*   ei    = (const int*)d_in[18];

    const int E = in_sizes[18] / 2;
    const int M0 = in_sizes[0] / 256;   // 30000
    const int M1 = in_sizes[1] / 128;   // 20000
    const int* src = ei;
    const int* dst = ei + E;

    float *bufA, *bufB, *elA, *erA, *elB, *erB;
    __nv_bfloat16 *fhi, *flo, *hhi, *hlo, *ahi, *alo;
    __nv_bfloat16 *wf0h, *wf0l, *wf1h, *wf1l, *w0th, *w0tl, *w1th, *w1tl;
    cudaGetSymbolAddress((void**)&bufA, g_bufA);
    cudaGetSymbolAddress((void**)&bufB, g_bufB);
    cudaGetSymbolAddress((void**)&elA,  g_elA);
    cudaGetSymbolAddress((void**)&erA,  g_erA);
    cudaGetSymbolAddress((void**)&elB,  g_elB);
    cudaGetSymbolAddress((void**)&erB,  g_erB);
    cudaGetSymbolAddress((void**)&fhi,  g_f_hi);
    cudaGetSymbolAddress((void**)&flo,  g_f_lo);
    cudaGetSymbolAddress((void**)&hhi,  g_h_hi);
    cudaGetSymbolAddress((void**)&hlo,  g_h_lo);
    cudaGetSymbolAddress((void**)&ahi,  g_a_hi);
    cudaGetSymbolAddress((void**)&alo,  g_a_lo);
    cudaGetSymbolAddress((void**)&wf0h, g_wf0_hi);
    cudaGetSymbolAddress((void**)&wf0l, g_wf0_lo);
    cudaGetSymbolAddress((void**)&wf1h, g_wf1_hi);
    cudaGetSymbolAddress((void**)&wf1l, g_wf1_lo);
    cudaGetSymbolAddress((void**)&w0th, g_w0t_hi);
    cudaGetSymbolAddress((void**)&w0tl, g_w0t_lo);
    cudaGetSymbolAddress((void**)&w1th, g_w1t_hi);
    cudaGetSymbolAddress((void**)&w1tl, g_w1t_lo);

    float* outp = (float*)d_out;

    constexpr int SMEM_L = STG * (2 * TILEB + 2 * 128 * ROWB);   // 98304
    constexpr int SMEM_P = STG * (2 * TILEB + 2 * 64 * ROWB);    // 73728
    cudaFuncSetAttribute((const void*)&k_mma<256, 64, false, true>,
                         cudaFuncAttributeMaxDynamicSharedMemorySize, SMEM_P);
    cudaFuncSetAttribute((const void*)&k_mma<128, 64, false, true>,
                         cudaFuncAttributeMaxDynamicSharedMemorySize, SMEM_P);
    cudaFuncSetAttribute((const void*)&k_mma<64, 128, true, false>,
                         cudaFuncAttributeMaxDynamicSharedMemorySize, SMEM_L);
    cudaFuncSetAttribute((const void*)&k_mma<512, 128, true, false>,
                         cudaFuncAttributeMaxDynamicSharedMemorySize, SMEM_L);

    // fork side streams off the (possibly capturing) default stream
    cudaStream_t sB, sC;
    cudaStreamCreateWithFlags(&sB, cudaStreamNonBlocking);
    cudaStreamCreateWithFlags(&sC, cudaStreamNonBlocking);
    cudaEvent_t evFork, evB, evC;
    cudaEventCreateWithFlags(&evFork, cudaEventDisableTiming);
    cudaEventCreateWithFlags(&evB,    cudaEventDisableTiming);
    cudaEventCreateWithFlags(&evC,    cudaEventDisableTiming);
    cudaEventRecord(evFork, 0);
    cudaStreamWaitEvent(sB, evFork, 0);
    cudaStreamWaitEvent(sC, evFork, 0);

    // main stream, launches 0..3 (index 3 = profiled proj0 mma)
    k_asplit<<<(M0 * 256 / 4 + 255) / 256, 256>>>(feat0, fhi, flo, M0 * 256);
    k_asplit<<<(M1 * 128 / 4 + 255) / 256, 256>>>(feat1, fhi + F0SZ, flo + F0SZ, M1 * 128);
    k_tsplit<<<dim3(2, 8),  dim3(32, 32)>>>(fc0w, wf0h, wf0l, 256, 64);
    k_mma<256, 64, false, true><<<dim3(1, 235), 256, SMEM_P>>>(
        fhi, flo, wf0h, wf0l, nullptr, hhi, hlo, fc0b,
        nullptr, nullptr, nullptr, nullptr, M0);

    // side stream B: CSR build
    k_zero_deg<<<(NN + 255) / 256, 256, 0, sB>>>();
    k_count<<<(E + 255) / 256, 256, 0, sB>>>(dst, E);
    k_scan1<<<NBLK, 256, 0, sB>>>();
    k_scan2<<<1, 256, 0, sB>>>();
    k_scan3<<<NBLK, 256, 0, sB>>>();
    k_scatter<<<(E + 255) / 256, 256, 0, sB>>>(src, dst, E);
    cudaEventRecord(evB, sB);

    // side stream C: layer weight splits + el/er zero
    k_zero_el<<<(NN * HEADS + 255) / 256, 256, 0, sC>>>();
    k_tsplit<<<dim3(16, 2),  dim3(32, 32), 0, sC>>>(W0, w0th, w0tl, 64, 512);
    k_tsplit<<<dim3(16, 16), dim3(32, 32), 0, sC>>>(W1, w1th, w1tl, 512, 512);
    cudaEventRecord(evC, sC);

    // main stream continues: proj1
    k_tsplit<<<dim3(2, 4), dim3(32, 32)>>>(fc1w, wf1h, wf1l, 128, 64);
    k_mma<128, 64, false, true><<<dim3(1, 157), 256, SMEM_P>>>(
        fhi + F0SZ, flo + F0SZ, wf1h, wf1l, nullptr,
        hhi + (size_t)M0 * 64, hlo + (size_t)M0 * 64, fc1b,
        nullptr, nullptr, nullptr, nullptr, M1);

    // join C (W0/W1 splits + zeros) before layer-0 mma
    cudaStreamWaitEvent(0, evC, 0);
    k_mma<64, 128, true, false><<<dim3(4, 391), 256, SMEM_L>>>(
        hhi, hlo, w0th, w0tl, bufA, nullptr, nullptr, nullptr,
        al0, ar0, elA, erA, NN);

    // join B (CSR) before attention
    cudaStreamWaitEvent(0, evB, 0);
    k_attn<<<NN, dim3(32, HEADS)>>>(bufA, b0, elA, erA, ahi, alo);

    // layer 1
    k_mma<512, 128, true, false><<<dim3(4, 391), 256, SMEM_L>>>(
        ahi, alo, w1th, w1tl, bufA, nullptr, nullptr, nullptr,
        al1, ar1, elB, erB, NN);
    k_attn<<<NN, dim3(32, HEADS)>>>(bufA, b1, elB, erB, ahi, alo);

    // layer 2
    k_gemm_n10<<<(NN + 7) / 8, 256>>>(ahi, alo, W2, bufB, al2, ar2, elA, erA, NN);
    k_agg10<<<NN, 32>>>(bufB, b2, elA, erA, outp);

    cudaEventDestroy(evFork);
    cudaEventDestroy(evB);
    cudaEventDestroy(evC);
    cudaStreamDestroy(sB);
    cudaStreamDestroy(sC);

    (void)n_in; (void)out_size;
}